// round 1
// baseline (speedup 1.0000x reference)
#include <cuda_runtime.h>

#define NN   100000
#define NE   1600000
#define KDIM 128
#define NCLS 40

// ---------------- scratch (device globals; no allocation) ----------------
__device__ float4 g_agg[NN * 32];     // 51.2 MB  aggregation output (always GEMM input)
__device__ float4 g_h[NN * 32];       // 51.2 MB  hidden activations (GEMM output / agg input)
__device__ int    g_counts[NN];
__device__ int    g_rowptr[NN + 1];
__device__ int    g_cursor[NN];
__device__ int    g_esrc[NE];

// ---------------- CSR build ----------------
__global__ void k_zero() {
    int i = blockIdx.x * 256 + threadIdx.x;
    if (i < NN) g_counts[i] = 0;
}

__global__ void k_hist(const int* __restrict__ dst) {
    int i = blockIdx.x * 256 + threadIdx.x;
    if (i < NE) atomicAdd(&g_counts[dst[i]], 1);
}

// Single-block exclusive scan of g_counts -> g_rowptr (+ cursor copy).
__global__ void k_scan() {
    __shared__ int sh[1024];
    int t = threadIdx.x;
    const int CH = (NN + 1023) / 1024;  // 98
    int b = t * CH;
    int e = min(b + CH, NN);
    int s = 0;
    for (int i = b; i < e; i++) s += g_counts[i];
    sh[t] = s;
    __syncthreads();
    for (int off = 1; off < 1024; off <<= 1) {
        int v = (t >= off) ? sh[t - off] : 0;
        __syncthreads();
        sh[t] += v;
        __syncthreads();
    }
    int run = sh[t] - s;  // exclusive prefix
    for (int i = b; i < e; i++) {
        g_rowptr[i] = run;
        g_cursor[i] = run;
        run += g_counts[i];
    }
    if (t == 1023) g_rowptr[NN] = sh[1023];
}

__global__ void k_scatter(const int* __restrict__ src, const int* __restrict__ dst) {
    int i = blockIdx.x * 256 + threadIdx.x;
    if (i < NE) {
        int p = atomicAdd(&g_cursor[dst[i]], 1);
        g_esrc[p] = src[i];
    }
}

// ---------------- aggregation: one warp per destination node ----------------
// x row = 128 floats = 32 float4 -> one float4 per lane. No atomics.
__global__ void k_agg(const float4* __restrict__ xext) {
    int gw = (blockIdx.x * blockDim.x + threadIdx.x) >> 5;
    if (gw >= NN) return;
    const float4* __restrict__ x = xext ? xext : g_h;
    int lane = threadIdx.x & 31;
    int beg = g_rowptr[gw], end = g_rowptr[gw + 1];

    float4 a0 = make_float4(0.f, 0.f, 0.f, 0.f);
    float4 a1 = a0, a2 = a0, a3 = a0;

    int e = beg;
    for (; e + 4 <= end; e += 4) {
        int s0 = __ldg(&g_esrc[e + 0]);
        int s1 = __ldg(&g_esrc[e + 1]);
        int s2 = __ldg(&g_esrc[e + 2]);
        int s3 = __ldg(&g_esrc[e + 3]);
        float4 v0 = __ldg(&x[(size_t)s0 * 32 + lane]);
        float4 v1 = __ldg(&x[(size_t)s1 * 32 + lane]);
        float4 v2 = __ldg(&x[(size_t)s2 * 32 + lane]);
        float4 v3 = __ldg(&x[(size_t)s3 * 32 + lane]);
        a0.x += v0.x; a0.y += v0.y; a0.z += v0.z; a0.w += v0.w;
        a1.x += v1.x; a1.y += v1.y; a1.z += v1.z; a1.w += v1.w;
        a2.x += v2.x; a2.y += v2.y; a2.z += v2.z; a2.w += v2.w;
        a3.x += v3.x; a3.y += v3.y; a3.z += v3.z; a3.w += v3.w;
    }
    for (; e < end; e++) {
        int s = __ldg(&g_esrc[e]);
        float4 v = __ldg(&x[(size_t)s * 32 + lane]);
        a0.x += v.x; a0.y += v.y; a0.z += v.z; a0.w += v.w;
    }
    float4 r;
    r.x = (a0.x + a1.x) + (a2.x + a3.x);
    r.y = (a0.y + a1.y) + (a2.y + a3.y);
    r.z = (a0.z + a1.z) + (a2.z + a3.z);
    r.w = (a0.w + a1.w) + (a2.w + a3.w);
    g_agg[(size_t)gw * 32 + lane] = r;
}

// ---------------- GEMM + bias + relu ----------------
// C[M,N] = relu(g_agg[M,128] @ W[128,N] + bias). BM=128, BN=64, BK=16.
// 256 threads, each computes 8x4. If Cext == nullptr -> write g_h.
__global__ void __launch_bounds__(256) k_gemm(const float* __restrict__ W,
                                              const float* __restrict__ bias,
                                              float* __restrict__ Cext, int N) {
    __shared__ float As[16][132];
    __shared__ float Bs[16][68];
    const float* __restrict__ A = (const float*)g_agg;
    float* __restrict__ C = Cext ? Cext : (float*)g_h;

    int t = threadIdx.x;
    int tx = t & 15, ty = t >> 4;
    int m0 = blockIdx.x * 128, n0 = blockIdx.y * 64;

    float acc[8][4];
#pragma unroll
    for (int i = 0; i < 8; i++)
#pragma unroll
        for (int j = 0; j < 4; j++) acc[i][j] = 0.f;

    for (int kc = 0; kc < 8; kc++) {
        // load A tile 128x16 (float4 along K), transpose into As[k][row]
#pragma unroll
        for (int i = 0; i < 2; i++) {
            int f = t + i * 256;
            int row = f >> 2, kq = f & 3;
            float4 v = make_float4(0.f, 0.f, 0.f, 0.f);
            if (m0 + row < NN)
                v = *(const float4*)(A + (size_t)(m0 + row) * KDIM + kc * 16 + kq * 4);
            As[kq * 4 + 0][row] = v.x;
            As[kq * 4 + 1][row] = v.y;
            As[kq * 4 + 2][row] = v.z;
            As[kq * 4 + 3][row] = v.w;
        }
        // load B tile 16x64 (scalar, predicated on N)
        {
            int r = t >> 4, cq = t & 15;
#pragma unroll
            for (int j = 0; j < 4; j++) {
                int col = n0 + cq * 4 + j;
                Bs[r][cq * 4 + j] = (col < N) ? W[(size_t)(kc * 16 + r) * N + col] : 0.f;
            }
        }
        __syncthreads();
#pragma unroll
        for (int kk = 0; kk < 16; kk++) {
            float4 aA = *(const float4*)&As[kk][ty * 8];
            float4 aB = *(const float4*)&As[kk][ty * 8 + 4];
            float4 bv = *(const float4*)&Bs[kk][tx * 4];
            float a[8] = {aA.x, aA.y, aA.z, aA.w, aB.x, aB.y, aB.z, aB.w};
            float b[4] = {bv.x, bv.y, bv.z, bv.w};
#pragma unroll
            for (int i = 0; i < 8; i++)
#pragma unroll
                for (int j = 0; j < 4; j++) acc[i][j] = fmaf(a[i], b[j], acc[i][j]);
        }
        __syncthreads();
    }
#pragma unroll
    for (int i = 0; i < 8; i++) {
        int row = m0 + ty * 8 + i;
        if (row < NN) {
#pragma unroll
            for (int j = 0; j < 4; j++) {
                int col = n0 + tx * 4 + j;
                if (col < N)
                    C[(size_t)row * N + col] = fmaxf(acc[i][j] + bias[col], 0.f);
            }
        }
    }
}

// ---------------- launch ----------------
extern "C" void kernel_launch(void* const* d_in, const int* in_sizes, int n_in,
                              void* d_out, int out_size) {
    const float* feats = (const float*)d_in[0];
    const int*   src   = (const int*)d_in[1];
    const int*   dst   = (const int*)d_in[2];
    const float* W1 = (const float*)d_in[3];
    const float* b1 = (const float*)d_in[4];
    const float* W2 = (const float*)d_in[5];
    const float* b2 = (const float*)d_in[6];
    const float* W3 = (const float*)d_in[7];
    const float* b3 = (const float*)d_in[8];
    float* out = (float*)d_out;

    // CSR build (amortized over 3 aggregations)
    k_zero<<<(NN + 255) / 256, 256>>>();
    k_hist<<<(NE + 255) / 256, 256>>>(dst);
    k_scan<<<1, 1024>>>();
    k_scatter<<<(NE + 255) / 256, 256>>>(src, dst);

    const int AGG_BLOCKS = (NN * 32 + 255) / 256;  // 12500 (one warp per node)
    dim3 g12((NN + 127) / 128, 2);
    dim3 g3((NN + 127) / 128, 1);

    k_agg<<<AGG_BLOCKS, 256>>>((const float4*)feats);   // feats -> g_agg
    k_gemm<<<g12, 256>>>(W1, b1, nullptr, 128);         // g_agg -> g_h
    k_agg<<<AGG_BLOCKS, 256>>>(nullptr);                // g_h   -> g_agg
    k_gemm<<<g12, 256>>>(W2, b2, nullptr, 128);         // g_agg -> g_h
    k_agg<<<AGG_BLOCKS, 256>>>(nullptr);                // g_h   -> g_agg
    k_gemm<<<g3, 256>>>(W3, b3, out, NCLS);             // g_agg -> d_out
}

// round 6
// speedup vs baseline: 1.0034x; 1.0034x over previous
#include <cuda_runtime.h>

#define NN   100000
#define NE   1600000
#define KDIM 128
#define NCLS 40

// ---------------- scratch (device globals; device-code access ONLY) ----------
// NOTE: never pass these as host-side kernel arguments — in host code the name
// binds to the host shadow object (host pointer -> HMM migration -> mem-delta
// rule violation, rounds 2-4). Kernels reference the symbols directly.
__device__ float g_Z[NN * KDIM];      // 51.2 MB  GEMM output (agg input)
__device__ float g_A[NN * KDIM];      // 51.2 MB  agg output (next GEMM input)
__device__ int   g_counts[NN];
__device__ int   g_rowptr[NN + 1];
__device__ int   g_cursor[NN];
__device__ int   g_esrc[NE];

// ---------------- CSR build (round-1 proven, unchanged) ----------------
__global__ void k_zero() {
    int i = blockIdx.x * 256 + threadIdx.x;
    if (i < NN) g_counts[i] = 0;
}

__global__ void k_hist(const int* __restrict__ dst) {
    int i = blockIdx.x * 256 + threadIdx.x;
    if (i < NE) atomicAdd(&g_counts[dst[i]], 1);
}

__global__ void k_scan() {
    __shared__ int sh[1024];
    int t = threadIdx.x;
    const int CH = (NN + 1023) / 1024;  // 98
    int b = t * CH;
    int e = min(b + CH, NN);
    int s = 0;
    for (int i = b; i < e; i++) s += g_counts[i];
    sh[t] = s;
    __syncthreads();
    for (int off = 1; off < 1024; off <<= 1) {
        int v = (t >= off) ? sh[t - off] : 0;
        __syncthreads();
        sh[t] += v;
        __syncthreads();
    }
    int run = sh[t] - s;  // exclusive prefix
    for (int i = b; i < e; i++) {
        g_rowptr[i] = run;
        g_cursor[i] = run;
        run += g_counts[i];
    }
    if (t == 1023) g_rowptr[NN] = sh[1023];
}

__global__ void k_scatter(const int* __restrict__ src, const int* __restrict__ dst) {
    int i = blockIdx.x * 256 + threadIdx.x;
    if (i < NE) {
        int p = atomicAdd(&g_cursor[dst[i]], 1);
        g_esrc[p] = src[i];
    }
}

// ---------------- aggregation (128-dim) + bias + relu: g_Z -> g_A ------------
// One warp per destination node; one float4 per lane. Round-1 4-way unroll.
__global__ void k_agg_relu128(const float* __restrict__ bias) {
    int gw = (blockIdx.x * blockDim.x + threadIdx.x) >> 5;
    if (gw >= NN) return;
    const float4* __restrict__ x = (const float4*)g_Z;
    float4* __restrict__ outp = (float4*)g_A;
    int lane = threadIdx.x & 31;
    int beg = g_rowptr[gw], end = g_rowptr[gw + 1];

    float4 a0 = make_float4(0.f, 0.f, 0.f, 0.f);
    float4 a1 = a0, a2 = a0, a3 = a0;

    int e = beg;
    for (; e + 4 <= end; e += 4) {
        int s0 = __ldg(&g_esrc[e + 0]);
        int s1 = __ldg(&g_esrc[e + 1]);
        int s2 = __ldg(&g_esrc[e + 2]);
        int s3 = __ldg(&g_esrc[e + 3]);
        float4 v0 = __ldg(&x[(size_t)s0 * 32 + lane]);
        float4 v1 = __ldg(&x[(size_t)s1 * 32 + lane]);
        float4 v2 = __ldg(&x[(size_t)s2 * 32 + lane]);
        float4 v3 = __ldg(&x[(size_t)s3 * 32 + lane]);
        a0.x += v0.x; a0.y += v0.y; a0.z += v0.z; a0.w += v0.w;
        a1.x += v1.x; a1.y += v1.y; a1.z += v1.z; a1.w += v1.w;
        a2.x += v2.x; a2.y += v2.y; a2.z += v2.z; a2.w += v2.w;
        a3.x += v3.x; a3.y += v3.y; a3.z += v3.z; a3.w += v3.w;
    }
    for (; e < end; e++) {
        int s = __ldg(&g_esrc[e]);
        float4 v = __ldg(&x[(size_t)s * 32 + lane]);
        a0.x += v.x; a0.y += v.y; a0.z += v.z; a0.w += v.w;
    }
    float4 b = __ldg(&((const float4*)bias)[lane]);
    float4 r;
    r.x = fmaxf(((a0.x + a1.x) + (a2.x + a3.x)) + b.x, 0.f);
    r.y = fmaxf(((a0.y + a1.y) + (a2.y + a3.y)) + b.y, 0.f);
    r.z = fmaxf(((a0.z + a1.z) + (a2.z + a3.z)) + b.z, 0.f);
    r.w = fmaxf(((a0.w + a1.w) + (a2.w + a3.w)) + b.w, 0.f);
    outp[(size_t)gw * 32 + lane] = r;
}

// ---------------- aggregation (40-dim) + bias + relu: g_Z -> d_out -----------
// One warp per node; lane handles feature `lane`, and `lane+32` if < 40.
__global__ void k_agg_relu40(const float* __restrict__ bias,
                             float* __restrict__ outp) {
    int gw = (blockIdx.x * blockDim.x + threadIdx.x) >> 5;
    if (gw >= NN) return;
    const float* __restrict__ z = g_Z;
    int lane = threadIdx.x & 31;
    int f2 = lane + 32;
    bool has2 = f2 < NCLS;
    int beg = g_rowptr[gw], end = g_rowptr[gw + 1];

    float acc0a = 0.f, acc0b = 0.f, acc1a = 0.f, acc1b = 0.f;
    int e = beg;
    for (; e + 2 <= end; e += 2) {
        int s0 = __ldg(&g_esrc[e + 0]);
        int s1 = __ldg(&g_esrc[e + 1]);
        const float* r0 = z + (size_t)s0 * NCLS;
        const float* r1 = z + (size_t)s1 * NCLS;
        acc0a += __ldg(r0 + lane);
        acc0b += __ldg(r1 + lane);
        if (has2) {
            acc1a += __ldg(r0 + f2);
            acc1b += __ldg(r1 + f2);
        }
    }
    if (e < end) {
        int s = __ldg(&g_esrc[e]);
        const float* r0 = z + (size_t)s * NCLS;
        acc0a += __ldg(r0 + lane);
        if (has2) acc1a += __ldg(r0 + f2);
    }
    float* orow = outp + (size_t)gw * NCLS;
    orow[lane] = fmaxf((acc0a + acc0b) + __ldg(bias + lane), 0.f);
    if (has2) orow[f2] = fmaxf((acc1a + acc1b) + __ldg(bias + f2), 0.f);
}

// ---------------- GEMM (round-1 proven tile): C = A[M,128] @ W[128,N] --------
// BM=128, BN=64, BK=16, 256 threads, 8x4 per thread.
// A: external (Aext) if non-null, else g_A. C: external (Cext) if non-null,
// else g_Z. Device symbols touched only in device code.
__global__ void __launch_bounds__(256) k_gemm(const float* __restrict__ Aext,
                                              const float* __restrict__ W,
                                              float* __restrict__ Cext, int N) {
    __shared__ float As[16][132];
    __shared__ float Bs[16][68];
    const float* __restrict__ A = Aext ? Aext : g_A;
    float* __restrict__ C = Cext ? Cext : g_Z;

    int t = threadIdx.x;
    int tx = t & 15, ty = t >> 4;
    int m0 = blockIdx.x * 128, n0 = blockIdx.y * 64;

    float acc[8][4];
#pragma unroll
    for (int i = 0; i < 8; i++)
#pragma unroll
        for (int j = 0; j < 4; j++) acc[i][j] = 0.f;

    for (int kc = 0; kc < 8; kc++) {
        // load A tile 128x16 (float4 along K), transpose into As[k][row]
#pragma unroll
        for (int i = 0; i < 2; i++) {
            int f = t + i * 256;
            int row = f >> 2, kq = f & 3;
            float4 v = make_float4(0.f, 0.f, 0.f, 0.f);
            if (m0 + row < NN)
                v = *(const float4*)(A + (size_t)(m0 + row) * KDIM + kc * 16 + kq * 4);
            As[kq * 4 + 0][row] = v.x;
            As[kq * 4 + 1][row] = v.y;
            As[kq * 4 + 2][row] = v.z;
            As[kq * 4 + 3][row] = v.w;
        }
        // load B tile 16x64 (scalar, predicated on N)
        {
            int r = t >> 4, cq = t & 15;
#pragma unroll
            for (int j = 0; j < 4; j++) {
                int col = n0 + cq * 4 + j;
                Bs[r][cq * 4 + j] = (col < N) ? W[(size_t)(kc * 16 + r) * N + col] : 0.f;
            }
        }
        __syncthreads();
#pragma unroll
        for (int kk = 0; kk < 16; kk++) {
            float4 aA = *(const float4*)&As[kk][ty * 8];
            float4 aB = *(const float4*)&As[kk][ty * 8 + 4];
            float4 bv = *(const float4*)&Bs[kk][tx * 4];
            float a[8] = {aA.x, aA.y, aA.z, aA.w, aB.x, aB.y, aB.z, aB.w};
            float b[4] = {bv.x, bv.y, bv.z, bv.w};
#pragma unroll
            for (int i = 0; i < 8; i++)
#pragma unroll
                for (int j = 0; j < 4; j++) acc[i][j] = fmaf(a[i], b[j], acc[i][j]);
        }
        __syncthreads();
    }
#pragma unroll
    for (int i = 0; i < 8; i++) {
        int row = m0 + ty * 8 + i;
        if (row < NN) {
#pragma unroll
            for (int j = 0; j < 4; j++) {
                int col = n0 + tx * 4 + j;
                if (col < N)
                    C[(size_t)row * N + col] = acc[i][j];
            }
        }
    }
}

// ---------------- launch ----------------
extern "C" void kernel_launch(void* const* d_in, const int* in_sizes, int n_in,
                              void* d_out, int out_size) {
    const float* feats = (const float*)d_in[0];
    const int*   src   = (const int*)d_in[1];
    const int*   dst   = (const int*)d_in[2];
    const float* W1 = (const float*)d_in[3];
    const float* b1 = (const float*)d_in[4];
    const float* W2 = (const float*)d_in[5];
    const float* b2 = (const float*)d_in[6];
    const float* W3 = (const float*)d_in[7];
    const float* b3 = (const float*)d_in[8];
    float* out = (float*)d_out;

    // CSR build (amortized over 3 aggregations)
    k_zero<<<(NN + 255) / 256, 256>>>();
    k_hist<<<(NE + 255) / 256, 256>>>(dst);
    k_scan<<<1, 1024>>>();
    k_scatter<<<(NE + 255) / 256, 256>>>(src, dst);

    const int AGG_BLOCKS = (NN * 32 + 255) / 256;  // one warp per node
    dim3 g12((NN + 127) / 128, 2);                 // N=128 -> 2 column tiles
    dim3 g3((NN + 127) / 128, 1);                  // N=40  -> 1 column tile

    // Layer 1: Z = feats@W1 ; A = relu(agg(Z) + b1)
    k_gemm<<<g12, 256>>>(feats, W1, nullptr, KDIM);   // feats -> g_Z
    k_agg_relu128<<<AGG_BLOCKS, 256>>>(b1);           // g_Z -> g_A
    // Layer 2
    k_gemm<<<g12, 256>>>(nullptr, W2, nullptr, KDIM); // g_A -> g_Z
    k_agg_relu128<<<AGG_BLOCKS, 256>>>(b2);           // g_Z -> g_A
    // Layer 3: project to 40 dims first, then aggregate 40-dim rows
    k_gemm<<<g3, 256>>>(nullptr, W3, nullptr, NCLS);  // g_A -> g_Z (40-dim rows)
    k_agg_relu40<<<AGG_BLOCKS, 256>>>(b3, out);       // g_Z -> d_out
}

// round 7
// speedup vs baseline: 1.3941x; 1.3893x over previous
#include <cuda_runtime.h>

#define NN   100000
#define NE   1600000
#define KDIM 128
#define NCLS 40

// ---------------- scratch (device globals; device-code access ONLY) ----------
// NOTE: never pass these as host-side kernel arguments — host code binds the
// host shadow object (HMM migration -> mem-delta violation, rounds 2-4).
__device__ float g_Z[NN * KDIM];      // 51.2 MB  GEMM output (agg input)
__device__ float g_A[NN * KDIM];      // 51.2 MB  agg output (next GEMM input)
__device__ int   g_counts[NN];
__device__ int   g_rowbeg[NN];
__device__ int   g_cursor[NN];
__device__ int   g_esrc[NE];
__device__ int   g_total;

// ---------------- CSR build ----------------
__global__ void k_zero() {
    int i = blockIdx.x * 256 + threadIdx.x;
    if (i < NN) g_counts[i] = 0;
    if (i == 0) g_total = 0;
}

__global__ void k_hist(const int* __restrict__ dst) {
    int i = blockIdx.x * 256 + threadIdx.x;
    if (i < NE) atomicAdd(&g_counts[dst[i]], 1);
}

// Per-node segment base via one global atomic (replaces 1-block serial scan).
// Segment placement order is arbitrary; per-node edge sets are unchanged.
__global__ void k_base() {
    int v = blockIdx.x * 256 + threadIdx.x;
    if (v < NN) {
        int c = g_counts[v];
        int b = atomicAdd(&g_total, c);
        g_rowbeg[v] = b;
        g_cursor[v] = b;
    }
}

__global__ void k_scatter(const int* __restrict__ src, const int* __restrict__ dst) {
    int i = blockIdx.x * 256 + threadIdx.x;
    if (i < NE) {
        int p = atomicAdd(&g_cursor[dst[i]], 1);
        g_esrc[p] = src[i];
    }
}

// ---------------- aggregation (128-dim) + bias + relu: g_Z -> g_A ------------
// One warp per destination node; one float4 per lane. 4-way unroll.
__global__ void k_agg_relu128(const float* __restrict__ bias) {
    int gw = (blockIdx.x * blockDim.x + threadIdx.x) >> 5;
    if (gw >= NN) return;
    const float4* __restrict__ x = (const float4*)g_Z;
    float4* __restrict__ outp = (float4*)g_A;
    int lane = threadIdx.x & 31;
    int beg = g_rowbeg[gw];
    int end = beg + g_counts[gw];

    float4 a0 = make_float4(0.f, 0.f, 0.f, 0.f);
    float4 a1 = a0, a2 = a0, a3 = a0;

    int e = beg;
    for (; e + 4 <= end; e += 4) {
        int s0 = __ldg(&g_esrc[e + 0]);
        int s1 = __ldg(&g_esrc[e + 1]);
        int s2 = __ldg(&g_esrc[e + 2]);
        int s3 = __ldg(&g_esrc[e + 3]);
        float4 v0 = __ldg(&x[(size_t)s0 * 32 + lane]);
        float4 v1 = __ldg(&x[(size_t)s1 * 32 + lane]);
        float4 v2 = __ldg(&x[(size_t)s2 * 32 + lane]);
        float4 v3 = __ldg(&x[(size_t)s3 * 32 + lane]);
        a0.x += v0.x; a0.y += v0.y; a0.z += v0.z; a0.w += v0.w;
        a1.x += v1.x; a1.y += v1.y; a1.z += v1.z; a1.w += v1.w;
        a2.x += v2.x; a2.y += v2.y; a2.z += v2.z; a2.w += v2.w;
        a3.x += v3.x; a3.y += v3.y; a3.z += v3.z; a3.w += v3.w;
    }
    for (; e < end; e++) {
        int s = __ldg(&g_esrc[e]);
        float4 v = __ldg(&x[(size_t)s * 32 + lane]);
        a0.x += v.x; a0.y += v.y; a0.z += v.z; a0.w += v.w;
    }
    float4 b = __ldg(&((const float4*)bias)[lane]);
    float4 r;
    r.x = fmaxf(((a0.x + a1.x) + (a2.x + a3.x)) + b.x, 0.f);
    r.y = fmaxf(((a0.y + a1.y) + (a2.y + a3.y)) + b.y, 0.f);
    r.z = fmaxf(((a0.z + a1.z) + (a2.z + a3.z)) + b.z, 0.f);
    r.w = fmaxf(((a0.w + a1.w) + (a2.w + a3.w)) + b.w, 0.f);
    outp[(size_t)gw * 32 + lane] = r;
}

// ---------------- aggregation (40-dim) + bias + relu: g_Z -> d_out -----------
__global__ void k_agg_relu40(const float* __restrict__ bias,
                             float* __restrict__ outp) {
    int gw = (blockIdx.x * blockDim.x + threadIdx.x) >> 5;
    if (gw >= NN) return;
    const float* __restrict__ z = g_Z;
    int lane = threadIdx.x & 31;
    int f2 = lane + 32;
    bool has2 = f2 < NCLS;
    int beg = g_rowbeg[gw];
    int end = beg + g_counts[gw];

    float acc0a = 0.f, acc0b = 0.f, acc1a = 0.f, acc1b = 0.f;
    int e = beg;
    for (; e + 2 <= end; e += 2) {
        int s0 = __ldg(&g_esrc[e + 0]);
        int s1 = __ldg(&g_esrc[e + 1]);
        const float* r0 = z + (size_t)s0 * NCLS;
        const float* r1 = z + (size_t)s1 * NCLS;
        acc0a += __ldg(r0 + lane);
        acc0b += __ldg(r1 + lane);
        if (has2) {
            acc1a += __ldg(r0 + f2);
            acc1b += __ldg(r1 + f2);
        }
    }
    if (e < end) {
        int s = __ldg(&g_esrc[e]);
        const float* r0 = z + (size_t)s * NCLS;
        acc0a += __ldg(r0 + lane);
        if (has2) acc1a += __ldg(r0 + f2);
    }
    float* orow = outp + (size_t)gw * NCLS;
    orow[lane] = fmaxf((acc0a + acc0b) + __ldg(bias + lane), 0.f);
    if (has2) orow[f2] = fmaxf((acc1a + acc1b) + __ldg(bias + f2), 0.f);
}

// ---------------- GEMM (proven tile): C = A[M,128] @ W[128,N] ----------------
// BM=128, BN=64, BK=16, 256 threads, 8x4 per thread.
__global__ void __launch_bounds__(256) k_gemm(const float* __restrict__ Aext,
                                              const float* __restrict__ W,
                                              float* __restrict__ Cext, int N) {
    __shared__ float As[16][132];
    __shared__ float Bs[16][68];
    const float* __restrict__ A = Aext ? Aext : g_A;
    float* __restrict__ C = Cext ? Cext : g_Z;

    int t = threadIdx.x;
    int tx = t & 15, ty = t >> 4;
    int m0 = blockIdx.x * 128, n0 = blockIdx.y * 64;

    float acc[8][4];
#pragma unroll
    for (int i = 0; i < 8; i++)
#pragma unroll
        for (int j = 0; j < 4; j++) acc[i][j] = 0.f;

    for (int kc = 0; kc < 8; kc++) {
#pragma unroll
        for (int i = 0; i < 2; i++) {
            int f = t + i * 256;
            int row = f >> 2, kq = f & 3;
            float4 v = make_float4(0.f, 0.f, 0.f, 0.f);
            if (m0 + row < NN)
                v = *(const float4*)(A + (size_t)(m0 + row) * KDIM + kc * 16 + kq * 4);
            As[kq * 4 + 0][row] = v.x;
            As[kq * 4 + 1][row] = v.y;
            As[kq * 4 + 2][row] = v.z;
            As[kq * 4 + 3][row] = v.w;
        }
        {
            int r = t >> 4, cq = t & 15;
#pragma unroll
            for (int j = 0; j < 4; j++) {
                int col = n0 + cq * 4 + j;
                Bs[r][cq * 4 + j] = (col < N) ? W[(size_t)(kc * 16 + r) * N + col] : 0.f;
            }
        }
        __syncthreads();
#pragma unroll
        for (int kk = 0; kk < 16; kk++) {
            float4 aA = *(const float4*)&As[kk][ty * 8];
            float4 aB = *(const float4*)&As[kk][ty * 8 + 4];
            float4 bv = *(const float4*)&Bs[kk][tx * 4];
            float a[8] = {aA.x, aA.y, aA.z, aA.w, aB.x, aB.y, aB.z, aB.w};
            float b[4] = {bv.x, bv.y, bv.z, bv.w};
#pragma unroll
            for (int i = 0; i < 8; i++)
#pragma unroll
                for (int j = 0; j < 4; j++) acc[i][j] = fmaf(a[i], b[j], acc[i][j]);
        }
        __syncthreads();
    }
#pragma unroll
    for (int i = 0; i < 8; i++) {
        int row = m0 + ty * 8 + i;
        if (row < NN) {
#pragma unroll
            for (int j = 0; j < 4; j++) {
                int col = n0 + tx * 4 + j;
                if (col < N)
                    C[(size_t)row * N + col] = acc[i][j];
            }
        }
    }
}

// ---------------- launch ----------------
extern "C" void kernel_launch(void* const* d_in, const int* in_sizes, int n_in,
                              void* d_out, int out_size) {
    const float* feats = (const float*)d_in[0];
    const int*   src   = (const int*)d_in[1];
    const int*   dst   = (const int*)d_in[2];
    const float* W1 = (const float*)d_in[3];
    const float* b1 = (const float*)d_in[4];
    const float* W2 = (const float*)d_in[5];
    const float* b2 = (const float*)d_in[6];
    const float* W3 = (const float*)d_in[7];
    const float* b3 = (const float*)d_in[8];
    float* out = (float*)d_out;

    // One-time resource init (first call is the non-captured correctness run;
    // nothing is created during graph capture).
    static cudaStream_t s1 = nullptr;
    static cudaEvent_t  eFork = nullptr, eJoin = nullptr;
    if (!s1) {
        cudaStreamCreateWithFlags(&s1, cudaStreamNonBlocking);
        cudaEventCreateWithFlags(&eFork, cudaEventDisableTiming);
        cudaEventCreateWithFlags(&eJoin, cudaEventDisableTiming);
    }

    const int AGG_BLOCKS = (NN * 32 + 255) / 256;  // one warp per node
    dim3 g12((NN + 127) / 128, 2);                 // N=128 -> 2 column tiles
    dim3 g3((NN + 127) / 128, 1);                  // N=40  -> 1 column tile

    // Fork: CSR build on s1, concurrent with GEMM1 on the main stream.
    cudaEventRecord(eFork, 0);
    cudaStreamWaitEvent(s1, eFork, 0);
    k_zero<<<(NN + 255) / 256, 256, 0, s1>>>();
    k_hist<<<(NE + 255) / 256, 256, 0, s1>>>(dst);
    k_base<<<(NN + 255) / 256, 256, 0, s1>>>();
    k_scatter<<<(NE + 255) / 256, 256, 0, s1>>>(src, dst);
    cudaEventRecord(eJoin, s1);

    // Main stream: Layer-1 GEMM needs only feats/W1 (independent of CSR).
    k_gemm<<<g12, 256>>>(feats, W1, nullptr, KDIM);   // feats -> g_Z

    // Join: aggregation needs the CSR.
    cudaStreamWaitEvent(0, eJoin, 0);
    k_agg_relu128<<<AGG_BLOCKS, 256>>>(b1);           // g_Z -> g_A
    // Layer 2
    k_gemm<<<g12, 256>>>(nullptr, W2, nullptr, KDIM); // g_A -> g_Z
    k_agg_relu128<<<AGG_BLOCKS, 256>>>(b2);           // g_Z -> g_A
    // Layer 3: project to 40 dims first, then aggregate 40-dim rows
    k_gemm<<<g3, 256>>>(nullptr, W3, nullptr, NCLS);  // g_A -> g_Z (40-dim rows)
    k_agg_relu40<<<AGG_BLOCKS, 256>>>(b3, out);       // g_Z -> d_out
}

// round 8
// speedup vs baseline: 1.4086x; 1.0104x over previous
#include <cuda_runtime.h>

#define NN   100000
#define NE   1600000
#define KDIM 128
#define NCLS 40

// ---------------- scratch (device globals; device-code access ONLY) ----------
// NOTE: never pass these as host-side kernel arguments — host code binds the
// host shadow object (HMM migration -> mem-delta violation, rounds 2-4).
__device__ float g_Z[NN * KDIM];      // 51.2 MB  GEMM output (agg input)
__device__ float g_A[NN * KDIM];      // 51.2 MB  agg output (next GEMM input)
__device__ int   g_counts[NN];
__device__ int   g_rowbeg[NN];
__device__ int   g_cursor[NN];
__device__ int   g_esrc[NE];
__device__ int   g_total;

// ---------------- CSR build ----------------
__global__ void k_zero() {
    int i = blockIdx.x * 256 + threadIdx.x;
    if (i < NN) g_counts[i] = 0;
    if (i == 0) g_total = 0;
}

__global__ void k_hist(const int* __restrict__ dst) {
    int i = blockIdx.x * 256 + threadIdx.x;
    if (i < NE) atomicAdd(&g_counts[dst[i]], 1);
}

// Per-node segment base via one global atomic (order arbitrary; sets exact).
__global__ void k_base() {
    int v = blockIdx.x * 256 + threadIdx.x;
    if (v < NN) {
        int c = g_counts[v];
        int b = atomicAdd(&g_total, c);
        g_rowbeg[v] = b;
        g_cursor[v] = b;
    }
}

__global__ void k_scatter(const int* __restrict__ src, const int* __restrict__ dst) {
    int i = blockIdx.x * 256 + threadIdx.x;
    if (i < NE) {
        int p = atomicAdd(&g_cursor[dst[i]], 1);
        g_esrc[p] = src[i];
    }
}

// ---------------- aggregation (128-dim) + bias + relu: g_Z -> g_A ------------
// One warp per destination node; one float4 per lane. 4-way unroll.
__global__ void k_agg_relu128(const float* __restrict__ bias) {
    int gw = (blockIdx.x * blockDim.x + threadIdx.x) >> 5;
    if (gw >= NN) return;
    const float4* __restrict__ x = (const float4*)g_Z;
    float4* __restrict__ outp = (float4*)g_A;
    int lane = threadIdx.x & 31;
    int beg = g_rowbeg[gw];
    int end = beg + g_counts[gw];

    float4 a0 = make_float4(0.f, 0.f, 0.f, 0.f);
    float4 a1 = a0, a2 = a0, a3 = a0;

    int e = beg;
    for (; e + 4 <= end; e += 4) {
        int s0 = __ldg(&g_esrc[e + 0]);
        int s1 = __ldg(&g_esrc[e + 1]);
        int s2 = __ldg(&g_esrc[e + 2]);
        int s3 = __ldg(&g_esrc[e + 3]);
        float4 v0 = __ldg(&x[(size_t)s0 * 32 + lane]);
        float4 v1 = __ldg(&x[(size_t)s1 * 32 + lane]);
        float4 v2 = __ldg(&x[(size_t)s2 * 32 + lane]);
        float4 v3 = __ldg(&x[(size_t)s3 * 32 + lane]);
        a0.x += v0.x; a0.y += v0.y; a0.z += v0.z; a0.w += v0.w;
        a1.x += v1.x; a1.y += v1.y; a1.z += v1.z; a1.w += v1.w;
        a2.x += v2.x; a2.y += v2.y; a2.z += v2.z; a2.w += v2.w;
        a3.x += v3.x; a3.y += v3.y; a3.z += v3.z; a3.w += v3.w;
    }
    for (; e < end; e++) {
        int s = __ldg(&g_esrc[e]);
        float4 v = __ldg(&x[(size_t)s * 32 + lane]);
        a0.x += v.x; a0.y += v.y; a0.z += v.z; a0.w += v.w;
    }
    float4 b = __ldg(&((const float4*)bias)[lane]);
    float4 r;
    r.x = fmaxf(((a0.x + a1.x) + (a2.x + a3.x)) + b.x, 0.f);
    r.y = fmaxf(((a0.y + a1.y) + (a2.y + a3.y)) + b.y, 0.f);
    r.z = fmaxf(((a0.z + a1.z) + (a2.z + a3.z)) + b.z, 0.f);
    r.w = fmaxf(((a0.w + a1.w) + (a2.w + a3.w)) + b.w, 0.f);
    outp[(size_t)gw * 32 + lane] = r;
}

// ---------------- aggregation (40-dim) + bias + relu: g_Z -> d_out -----------
__global__ void k_agg_relu40(const float* __restrict__ bias,
                             float* __restrict__ outp) {
    int gw = (blockIdx.x * blockDim.x + threadIdx.x) >> 5;
    if (gw >= NN) return;
    const float* __restrict__ z = g_Z;
    int lane = threadIdx.x & 31;
    int f2 = lane + 32;
    bool has2 = f2 < NCLS;
    int beg = g_rowbeg[gw];
    int end = beg + g_counts[gw];

    float acc0a = 0.f, acc0b = 0.f, acc1a = 0.f, acc1b = 0.f;
    int e = beg;
    for (; e + 2 <= end; e += 2) {
        int s0 = __ldg(&g_esrc[e + 0]);
        int s1 = __ldg(&g_esrc[e + 1]);
        const float* r0 = z + (size_t)s0 * NCLS;
        const float* r1 = z + (size_t)s1 * NCLS;
        acc0a += __ldg(r0 + lane);
        acc0b += __ldg(r1 + lane);
        if (has2) {
            acc1a += __ldg(r0 + f2);
            acc1b += __ldg(r1 + f2);
        }
    }
    if (e < end) {
        int s = __ldg(&g_esrc[e]);
        const float* r0 = z + (size_t)s * NCLS;
        acc0a += __ldg(r0 + lane);
        if (has2) acc1a += __ldg(r0 + f2);
    }
    float* orow = outp + (size_t)gw * NCLS;
    orow[lane] = fmaxf((acc0a + acc0b) + __ldg(bias + lane), 0.f);
    if (has2) orow[f2] = fmaxf((acc1a + acc1b) + __ldg(bias + f2), 0.f);
}

// ---------------- GEMM 128-col: C[M,128] = A[M,128] @ W[128,128] -------------
// BM=128, BN=128, BK=16, 256 threads, 8x8 per thread. A read once per block.
__global__ void __launch_bounds__(256) k_gemm128(const float* __restrict__ Aext,
                                                 const float* __restrict__ W) {
    __shared__ float As[16][132];
    __shared__ float Bs[16][132];
    const float* __restrict__ A = Aext ? Aext : g_A;
    float* __restrict__ C = g_Z;

    int t = threadIdx.x;
    int tx = t & 15, ty = t >> 4;
    int m0 = blockIdx.x * 128;

    float acc[8][8];
#pragma unroll
    for (int i = 0; i < 8; i++)
#pragma unroll
        for (int j = 0; j < 8; j++) acc[i][j] = 0.f;

    for (int kc = 0; kc < 8; kc++) {
        // A tile 128x16 (float4 along K) -> transposed As[k][m]
#pragma unroll
        for (int i = 0; i < 2; i++) {
            int f = t + i * 256;
            int row = f >> 2, kq = f & 3;
            float4 v = make_float4(0.f, 0.f, 0.f, 0.f);
            if (m0 + row < NN)
                v = *(const float4*)(A + (size_t)(m0 + row) * KDIM + kc * 16 + kq * 4);
            As[kq * 4 + 0][row] = v.x;
            As[kq * 4 + 1][row] = v.y;
            As[kq * 4 + 2][row] = v.z;
            As[kq * 4 + 3][row] = v.w;
        }
        // B tile 16x128 natural layout (2 float4 per thread)
#pragma unroll
        for (int i = 0; i < 2; i++) {
            int r = (t >> 5) + i * 8;
            int c = (t & 31) * 4;
            *(float4*)&Bs[r][c] = *(const float4*)(W + (size_t)(kc * 16 + r) * KDIM + c);
        }
        __syncthreads();
#pragma unroll
        for (int kk = 0; kk < 16; kk++) {
            float4 aA = *(const float4*)&As[kk][ty * 8];
            float4 aB = *(const float4*)&As[kk][ty * 8 + 4];
            float4 bA = *(const float4*)&Bs[kk][tx * 8];
            float4 bB = *(const float4*)&Bs[kk][tx * 8 + 4];
            float a[8] = {aA.x, aA.y, aA.z, aA.w, aB.x, aB.y, aB.z, aB.w};
            float b[8] = {bA.x, bA.y, bA.z, bA.w, bB.x, bB.y, bB.z, bB.w};
#pragma unroll
            for (int i = 0; i < 8; i++)
#pragma unroll
                for (int j = 0; j < 8; j++) acc[i][j] = fmaf(a[i], b[j], acc[i][j]);
        }
        __syncthreads();
    }
#pragma unroll
    for (int i = 0; i < 8; i++) {
        int row = m0 + ty * 8 + i;
        if (row < NN) {
            float4 lo = make_float4(acc[i][0], acc[i][1], acc[i][2], acc[i][3]);
            float4 hi = make_float4(acc[i][4], acc[i][5], acc[i][6], acc[i][7]);
            *(float4*)(C + (size_t)row * KDIM + tx * 8)     = lo;
            *(float4*)(C + (size_t)row * KDIM + tx * 8 + 4) = hi;
        }
    }
}

// ---------------- GEMM 40-col (proven BN=64 tile): g_A @ W3 -> g_Z -----------
__global__ void __launch_bounds__(256) k_gemm40(const float* __restrict__ W) {
    __shared__ float As[16][132];
    __shared__ float Bs[16][68];
    const float* __restrict__ A = g_A;
    float* __restrict__ C = g_Z;
    const int N = NCLS;

    int t = threadIdx.x;
    int tx = t & 15, ty = t >> 4;
    int m0 = blockIdx.x * 128;

    float acc[8][4];
#pragma unroll
    for (int i = 0; i < 8; i++)
#pragma unroll
        for (int j = 0; j < 4; j++) acc[i][j] = 0.f;

    for (int kc = 0; kc < 8; kc++) {
#pragma unroll
        for (int i = 0; i < 2; i++) {
            int f = t + i * 256;
            int row = f >> 2, kq = f & 3;
            float4 v = make_float4(0.f, 0.f, 0.f, 0.f);
            if (m0 + row < NN)
                v = *(const float4*)(A + (size_t)(m0 + row) * KDIM + kc * 16 + kq * 4);
            As[kq * 4 + 0][row] = v.x;
            As[kq * 4 + 1][row] = v.y;
            As[kq * 4 + 2][row] = v.z;
            As[kq * 4 + 3][row] = v.w;
        }
        {
            int r = t >> 4, cq = t & 15;
#pragma unroll
            for (int j = 0; j < 4; j++) {
                int col = cq * 4 + j;
                Bs[r][cq * 4 + j] = (col < N) ? W[(size_t)(kc * 16 + r) * N + col] : 0.f;
            }
        }
        __syncthreads();
#pragma unroll
        for (int kk = 0; kk < 16; kk++) {
            float4 aA = *(const float4*)&As[kk][ty * 8];
            float4 aB = *(const float4*)&As[kk][ty * 8 + 4];
            float4 bv = *(const float4*)&Bs[kk][tx * 4];
            float a[8] = {aA.x, aA.y, aA.z, aA.w, aB.x, aB.y, aB.z, aB.w};
            float b[4] = {bv.x, bv.y, bv.z, bv.w};
#pragma unroll
            for (int i = 0; i < 8; i++)
#pragma unroll
                for (int j = 0; j < 4; j++) acc[i][j] = fmaf(a[i], b[j], acc[i][j]);
        }
        __syncthreads();
    }
#pragma unroll
    for (int i = 0; i < 8; i++) {
        int row = m0 + ty * 8 + i;
        if (row < NN) {
#pragma unroll
            for (int j = 0; j < 4; j++) {
                int col = tx * 4 + j;
                if (col < N)
                    C[(size_t)row * N + col] = acc[i][j];
            }
        }
    }
}

// ---------------- launch ----------------
extern "C" void kernel_launch(void* const* d_in, const int* in_sizes, int n_in,
                              void* d_out, int out_size) {
    const float* feats = (const float*)d_in[0];
    const int*   src   = (const int*)d_in[1];
    const int*   dst   = (const int*)d_in[2];
    const float* W1 = (const float*)d_in[3];
    const float* b1 = (const float*)d_in[4];
    const float* W2 = (const float*)d_in[5];
    const float* b2 = (const float*)d_in[6];
    const float* W3 = (const float*)d_in[7];
    const float* b3 = (const float*)d_in[8];
    float* out = (float*)d_out;

    // One-time resource init (first call is the non-captured correctness run).
    static cudaStream_t s1 = nullptr;
    static cudaEvent_t  eFork = nullptr, eJoin = nullptr;
    if (!s1) {
        cudaStreamCreateWithFlags(&s1, cudaStreamNonBlocking);
        cudaEventCreateWithFlags(&eFork, cudaEventDisableTiming);
        cudaEventCreateWithFlags(&eJoin, cudaEventDisableTiming);
    }

    const int AGG_BLOCKS = (NN * 32 + 255) / 256;  // one warp per node
    const int GB = (NN + 127) / 128;               // 782

    // Fork: CSR build on s1, concurrent with GEMM1 on the main stream.
    cudaEventRecord(eFork, 0);
    cudaStreamWaitEvent(s1, eFork, 0);
    k_zero<<<(NN + 255) / 256, 256, 0, s1>>>();
    k_hist<<<(NE + 255) / 256, 256, 0, s1>>>(dst);
    k_base<<<(NN + 255) / 256, 256, 0, s1>>>();
    k_scatter<<<(NE + 255) / 256, 256, 0, s1>>>(src, dst);
    cudaEventRecord(eJoin, s1);

    // Main stream: Layer-1 GEMM needs only feats/W1 (independent of CSR).
    k_gemm128<<<GB, 256>>>(feats, W1);               // feats -> g_Z

    // Join: aggregation needs the CSR.
    cudaStreamWaitEvent(0, eJoin, 0);
    k_agg_relu128<<<AGG_BLOCKS, 256>>>(b1);          // g_Z -> g_A
    // Layer 2
    k_gemm128<<<GB, 256>>>(nullptr, W2);             // g_A -> g_Z
    k_agg_relu128<<<AGG_BLOCKS, 256>>>(b2);          // g_Z -> g_A
    // Layer 3: project to 40 dims first, then aggregate 40-dim rows
    k_gemm40<<<GB, 256>>>(W3);                       // g_A -> g_Z (40-dim rows)
    k_agg_relu40<<<AGG_BLOCKS, 256>>>(b3, out);      // g_Z -> d_out
}

// round 10
// speedup vs baseline: 1.5346x; 1.0895x over previous
#include <cuda_runtime.h>
#include <cuda_bf16.h>

#define NN   100000
#define NE   1600000
#define KDIM 128
#define NCLS 40

// ---------------- scratch (device globals; device-code access ONLY) ----------
// NOTE: never pass these as host-side kernel arguments — host code binds the
// host shadow object (HMM migration -> mem-delta violation, rounds 2-4).
__device__ uint4 g_Zh[NN * 16];       // 25.6 MB  bf16 Z rows (128 bf16 = 16 uint4)
__device__ float g_Z[NN * KDIM];      // 51.2 MB  fp32 Z (layer-3 40-dim path)
__device__ float g_A[NN * KDIM];      // 51.2 MB  agg output (next GEMM input)
__device__ int   g_counts[NN];
__device__ int   g_rowbeg[NN];
__device__ int   g_cursor[NN];
__device__ int   g_esrc[NE];
__device__ int   g_total;

// ---------------- CSR build ----------------
__global__ void k_zero() {
    int i = blockIdx.x * 256 + threadIdx.x;
    if (i < NN) g_counts[i] = 0;
    if (i == 0) g_total = 0;
}

__global__ void k_hist(const int* __restrict__ dst) {
    int i = blockIdx.x * 256 + threadIdx.x;
    if (i < NE) atomicAdd(&g_counts[dst[i]], 1);
}

// Per-node segment base via one global atomic (order arbitrary; sets exact).
__global__ void k_base() {
    int v = blockIdx.x * 256 + threadIdx.x;
    if (v < NN) {
        int c = g_counts[v];
        int b = atomicAdd(&g_total, c);
        g_rowbeg[v] = b;
        g_cursor[v] = b;
    }
}

__global__ void k_scatter(const int* __restrict__ src, const int* __restrict__ dst) {
    int i = blockIdx.x * 256 + threadIdx.x;
    if (i < NE) {
        int p = atomicAdd(&g_cursor[dst[i]], 1);
        g_esrc[p] = src[i];
    }
}

// ---------------- aggregation (128-dim, bf16 payload) + bias + relu ----------
// One warp per node. Lane l gathers 4 bf16 (8 B) per edge; fp32 accumulate.
// 8 edges in flight (bytes halved vs fp32 -> deeper MLP to stay bw-bound).
__device__ __forceinline__ void bf16x4_add(float4& a, uint2 v) {
    __nv_bfloat162 p0 = *reinterpret_cast<__nv_bfloat162*>(&v.x);
    __nv_bfloat162 p1 = *reinterpret_cast<__nv_bfloat162*>(&v.y);
    float2 f0 = __bfloat1622float2(p0);
    float2 f1 = __bfloat1622float2(p1);
    a.x += f0.x; a.y += f0.y; a.z += f1.x; a.w += f1.y;
}

__global__ void k_agg_relu128(const float* __restrict__ bias) {
    int gw = (blockIdx.x * blockDim.x + threadIdx.x) >> 5;
    if (gw >= NN) return;
    const uint2* __restrict__ x = (const uint2*)g_Zh;  // row = 32 uint2
    float4* __restrict__ outp = (float4*)g_A;
    int lane = threadIdx.x & 31;
    int beg = g_rowbeg[gw];
    int end = beg + g_counts[gw];

    float4 a0 = make_float4(0.f, 0.f, 0.f, 0.f);
    float4 a1 = a0, a2 = a0, a3 = a0;

    int e = beg;
    for (; e + 8 <= end; e += 8) {
        int s0 = __ldg(&g_esrc[e + 0]);
        int s1 = __ldg(&g_esrc[e + 1]);
        int s2 = __ldg(&g_esrc[e + 2]);
        int s3 = __ldg(&g_esrc[e + 3]);
        int s4 = __ldg(&g_esrc[e + 4]);
        int s5 = __ldg(&g_esrc[e + 5]);
        int s6 = __ldg(&g_esrc[e + 6]);
        int s7 = __ldg(&g_esrc[e + 7]);
        uint2 v0 = __ldg(&x[(size_t)s0 * 32 + lane]);
        uint2 v1 = __ldg(&x[(size_t)s1 * 32 + lane]);
        uint2 v2 = __ldg(&x[(size_t)s2 * 32 + lane]);
        uint2 v3 = __ldg(&x[(size_t)s3 * 32 + lane]);
        uint2 v4 = __ldg(&x[(size_t)s4 * 32 + lane]);
        uint2 v5 = __ldg(&x[(size_t)s5 * 32 + lane]);
        uint2 v6 = __ldg(&x[(size_t)s6 * 32 + lane]);
        uint2 v7 = __ldg(&x[(size_t)s7 * 32 + lane]);
        bf16x4_add(a0, v0); bf16x4_add(a1, v1);
        bf16x4_add(a2, v2); bf16x4_add(a3, v3);
        bf16x4_add(a0, v4); bf16x4_add(a1, v5);
        bf16x4_add(a2, v6); bf16x4_add(a3, v7);
    }
    for (; e < end; e++) {
        int s = __ldg(&g_esrc[e]);
        uint2 v = __ldg(&x[(size_t)s * 32 + lane]);
        bf16x4_add(a0, v);
    }
    float4 b = __ldg(&((const float4*)bias)[lane]);
    float4 r;
    r.x = fmaxf(((a0.x + a1.x) + (a2.x + a3.x)) + b.x, 0.f);
    r.y = fmaxf(((a0.y + a1.y) + (a2.y + a3.y)) + b.y, 0.f);
    r.z = fmaxf(((a0.z + a1.z) + (a2.z + a3.z)) + b.z, 0.f);
    r.w = fmaxf(((a0.w + a1.w) + (a2.w + a3.w)) + b.w, 0.f);
    outp[(size_t)gw * 32 + lane] = r;
}

// ---------------- aggregation (40-dim, fp32) + bias + relu: g_Z -> d_out -----
__global__ void k_agg_relu40(const float* __restrict__ bias,
                             float* __restrict__ outp) {
    int gw = (blockIdx.x * blockDim.x + threadIdx.x) >> 5;
    if (gw >= NN) return;
    const float* __restrict__ z = g_Z;
    int lane = threadIdx.x & 31;
    int f2 = lane + 32;
    bool has2 = f2 < NCLS;
    int beg = g_rowbeg[gw];
    int end = beg + g_counts[gw];

    float acc0a = 0.f, acc0b = 0.f, acc1a = 0.f, acc1b = 0.f;
    int e = beg;
    for (; e + 2 <= end; e += 2) {
        int s0 = __ldg(&g_esrc[e + 0]);
        int s1 = __ldg(&g_esrc[e + 1]);
        const float* r0 = z + (size_t)s0 * NCLS;
        const float* r1 = z + (size_t)s1 * NCLS;
        acc0a += __ldg(r0 + lane);
        acc0b += __ldg(r1 + lane);
        if (has2) {
            acc1a += __ldg(r0 + f2);
            acc1b += __ldg(r1 + f2);
        }
    }
    if (e < end) {
        int s = __ldg(&g_esrc[e]);
        const float* r0 = z + (size_t)s * NCLS;
        acc0a += __ldg(r0 + lane);
        if (has2) acc1a += __ldg(r0 + f2);
    }
    float* orow = outp + (size_t)gw * NCLS;
    orow[lane] = fmaxf((acc0a + acc0b) + __ldg(bias + lane), 0.f);
    if (has2) orow[f2] = fmaxf((acc1a + acc1b) + __ldg(bias + f2), 0.f);
}

// ---------------- GEMM 128-col -> bf16 Z: Zh[M,128] = A[M,128] @ W[128,128] --
// BM=128, BN=128, BK=16, 256 threads, 8x8 per thread. Epilogue packs bf16.
__global__ void __launch_bounds__(256) k_gemm128(const float* __restrict__ Aext,
                                                 const float* __restrict__ W) {
    __shared__ float As[16][132];
    __shared__ float Bs[16][132];
    const float* __restrict__ A = Aext ? Aext : g_A;

    int t = threadIdx.x;
    int tx = t & 15, ty = t >> 4;
    int m0 = blockIdx.x * 128;

    float acc[8][8];
#pragma unroll
    for (int i = 0; i < 8; i++)
#pragma unroll
        for (int j = 0; j < 8; j++) acc[i][j] = 0.f;

    for (int kc = 0; kc < 8; kc++) {
#pragma unroll
        for (int i = 0; i < 2; i++) {
            int f = t + i * 256;
            int row = f >> 2, kq = f & 3;
            float4 v = make_float4(0.f, 0.f, 0.f, 0.f);
            if (m0 + row < NN)
                v = *(const float4*)(A + (size_t)(m0 + row) * KDIM + kc * 16 + kq * 4);
            As[kq * 4 + 0][row] = v.x;
            As[kq * 4 + 1][row] = v.y;
            As[kq * 4 + 2][row] = v.z;
            As[kq * 4 + 3][row] = v.w;
        }
#pragma unroll
        for (int i = 0; i < 2; i++) {
            int r = (t >> 5) + i * 8;
            int c = (t & 31) * 4;
            *(float4*)&Bs[r][c] = *(const float4*)(W + (size_t)(kc * 16 + r) * KDIM + c);
        }
        __syncthreads();
#pragma unroll
        for (int kk = 0; kk < 16; kk++) {
            float4 aA = *(const float4*)&As[kk][ty * 8];
            float4 aB = *(const float4*)&As[kk][ty * 8 + 4];
            float4 bA = *(const float4*)&Bs[kk][tx * 8];
            float4 bB = *(const float4*)&Bs[kk][tx * 8 + 4];
            float a[8] = {aA.x, aA.y, aA.z, aA.w, aB.x, aB.y, aB.z, aB.w};
            float b[8] = {bA.x, bA.y, bA.z, bA.w, bB.x, bB.y, bB.z, bB.w};
#pragma unroll
            for (int i = 0; i < 8; i++)
#pragma unroll
                for (int j = 0; j < 8; j++) acc[i][j] = fmaf(a[i], b[j], acc[i][j]);
        }
        __syncthreads();
    }
    // epilogue: pack 8 fp32 -> 8 bf16 (16 B = one uint4) per row
#pragma unroll
    for (int i = 0; i < 8; i++) {
        int row = m0 + ty * 8 + i;
        if (row < NN) {
            __nv_bfloat162 p0 = __floats2bfloat162_rn(acc[i][0], acc[i][1]);
            __nv_bfloat162 p1 = __floats2bfloat162_rn(acc[i][2], acc[i][3]);
            __nv_bfloat162 p2 = __floats2bfloat162_rn(acc[i][4], acc[i][5]);
            __nv_bfloat162 p3 = __floats2bfloat162_rn(acc[i][6], acc[i][7]);
            uint4 w;
            w.x = *reinterpret_cast<unsigned*>(&p0);
            w.y = *reinterpret_cast<unsigned*>(&p1);
            w.z = *reinterpret_cast<unsigned*>(&p2);
            w.w = *reinterpret_cast<unsigned*>(&p3);
            g_Zh[(size_t)row * 16 + tx] = w;
        }
    }
}

// ---------------- GEMM 40-col (fp32): g_A @ W3 -> g_Z ------------------------
__global__ void __launch_bounds__(256) k_gemm40(const float* __restrict__ W) {
    __shared__ float As[16][132];
    __shared__ float Bs[16][68];
    const float* __restrict__ A = g_A;
    float* __restrict__ C = g_Z;
    const int N = NCLS;

    int t = threadIdx.x;
    int tx = t & 15, ty = t >> 4;
    int m0 = blockIdx.x * 128;

    float acc[8][4];
#pragma unroll
    for (int i = 0; i < 8; i++)
#pragma unroll
        for (int j = 0; j < 4; j++) acc[i][j] = 0.f;

    for (int kc = 0; kc < 8; kc++) {
#pragma unroll
        for (int i = 0; i < 2; i++) {
            int f = t + i * 256;
            int row = f >> 2, kq = f & 3;
            float4 v = make_float4(0.f, 0.f, 0.f, 0.f);
            if (m0 + row < NN)
                v = *(const float4*)(A + (size_t)(m0 + row) * KDIM + kc * 16 + kq * 4);
            As[kq * 4 + 0][row] = v.x;
            As[kq * 4 + 1][row] = v.y;
            As[kq * 4 + 2][row] = v.z;
            As[kq * 4 + 3][row] = v.w;
        }
        {
            int r = t >> 4, cq = t & 15;
#pragma unroll
            for (int j = 0; j < 4; j++) {
                int col = cq * 4 + j;
                Bs[r][cq * 4 + j] = (col < N) ? W[(size_t)(kc * 16 + r) * N + col] : 0.f;
            }
        }
        __syncthreads();
#pragma unroll
        for (int kk = 0; kk < 16; kk++) {
            float4 aA = *(const float4*)&As[kk][ty * 8];
            float4 aB = *(const float4*)&As[kk][ty * 8 + 4];
            float4 bv = *(const float4*)&Bs[kk][tx * 4];
            float a[8] = {aA.x, aA.y, aA.z, aA.w, aB.x, aB.y, aB.z, aB.w};
            float b[4] = {bv.x, bv.y, bv.z, bv.w};
#pragma unroll
            for (int i = 0; i < 8; i++)
#pragma unroll
                for (int j = 0; j < 4; j++) acc[i][j] = fmaf(a[i], b[j], acc[i][j]);
        }
        __syncthreads();
    }
#pragma unroll
    for (int i = 0; i < 8; i++) {
        int row = m0 + ty * 8 + i;
        if (row < NN) {
#pragma unroll
            for (int j = 0; j < 4; j++) {
                int col = tx * 4 + j;
                if (col < N)
                    C[(size_t)row * N + col] = acc[i][j];
            }
        }
    }
}

// ---------------- launch ----------------
extern "C" void kernel_launch(void* const* d_in, const int* in_sizes, int n_in,
                              void* d_out, int out_size) {
    const float* feats = (const float*)d_in[0];
    const int*   src   = (const int*)d_in[1];
    const int*   dst   = (const int*)d_in[2];
    const float* W1 = (const float*)d_in[3];
    const float* b1 = (const float*)d_in[4];
    const float* W2 = (const float*)d_in[5];
    const float* b2 = (const float*)d_in[6];
    const float* W3 = (const float*)d_in[7];
    const float* b3 = (const float*)d_in[8];
    float* out = (float*)d_out;

    // One-time resource init (first call is the non-captured correctness run).
    static cudaStream_t s1 = nullptr;
    static cudaEvent_t  eFork = nullptr, eJoin = nullptr;
    if (!s1) {
        cudaStreamCreateWithFlags(&s1, cudaStreamNonBlocking);
        cudaEventCreateWithFlags(&eFork, cudaEventDisableTiming);
        cudaEventCreateWithFlags(&eJoin, cudaEventDisableTiming);
    }

    const int AGG_BLOCKS = (NN * 32 + 255) / 256;  // one warp per node
    const int GB = (NN + 127) / 128;               // 782

    // Fork: CSR build on s1, concurrent with GEMM1 on the main stream.
    cudaEventRecord(eFork, 0);
    cudaStreamWaitEvent(s1, eFork, 0);
    k_zero<<<(NN + 255) / 256, 256, 0, s1>>>();
    k_hist<<<(NE + 255) / 256, 256, 0, s1>>>(dst);
    k_base<<<(NN + 255) / 256, 256, 0, s1>>>();
    k_scatter<<<(NE + 255) / 256, 256, 0, s1>>>(src, dst);
    cudaEventRecord(eJoin, s1);

    // Main stream: Layer-1 GEMM needs only feats/W1 (independent of CSR).
    k_gemm128<<<GB, 256>>>(feats, W1);               // feats -> g_Zh (bf16)

    // Join: aggregation needs the CSR.
    cudaStreamWaitEvent(0, eJoin, 0);
    k_agg_relu128<<<AGG_BLOCKS, 256>>>(b1);          // g_Zh -> g_A (fp32)
    // Layer 2
    k_gemm128<<<GB, 256>>>(nullptr, W2);             // g_A -> g_Zh (bf16)
    k_agg_relu128<<<AGG_BLOCKS, 256>>>(b2);          // g_Zh -> g_A (fp32)
    // Layer 3: full fp32 (cheap; avoids compounding quantization)
    k_gemm40<<<GB, 256>>>(W3);                       // g_A -> g_Z (40-dim fp32)
    k_agg_relu40<<<AGG_BLOCKS, 256>>>(b3, out);      // g_Z -> d_out
}

// round 11
// speedup vs baseline: 1.6756x; 1.0919x over previous
#include <cuda_runtime.h>
#include <cuda_bf16.h>

#define NN   100000
#define NE   1600000
#define KDIM 128
#define NCLS 40

// ---------------- scratch (device globals; device-code access ONLY) ----------
// NOTE: never pass these as host-side kernel arguments — host code binds the
// host shadow object (HMM migration -> mem-delta violation, rounds 2-4).
__device__ uint4 g_Zh[NN * 16];       // 25.6 MB  bf16 Z rows (128 bf16 = 16 uint4)
__device__ float g_Z[NN * KDIM];      // 51.2 MB  fp32 Z (layer-3 40-dim path)
__device__ float g_A[NN * KDIM];      // 51.2 MB  agg output (next GEMM input)
__device__ int   g_counts[NN];
__device__ int   g_rowbeg[NN];
__device__ int   g_cursor[NN];
__device__ int   g_esrc[NE];
__device__ int   g_total;

// ---------------- CSR build ----------------
__global__ void k_zero() {
    int i = blockIdx.x * 256 + threadIdx.x;
    if (i < NN) g_counts[i] = 0;
    if (i == 0) g_total = 0;
}

__global__ void k_hist(const int* __restrict__ dst) {
    int i = blockIdx.x * 256 + threadIdx.x;
    if (i < NE) atomicAdd(&g_counts[dst[i]], 1);
}

// Per-node segment base via one global atomic (order arbitrary; sets exact).
__global__ void k_base() {
    int v = blockIdx.x * 256 + threadIdx.x;
    if (v < NN) {
        int c = g_counts[v];
        int b = atomicAdd(&g_total, c);
        g_rowbeg[v] = b;
        g_cursor[v] = b;
    }
}

__global__ void k_scatter(const int* __restrict__ src, const int* __restrict__ dst) {
    int i = blockIdx.x * 256 + threadIdx.x;
    if (i < NE) {
        int p = atomicAdd(&g_cursor[dst[i]], 1);
        g_esrc[p] = src[i];
    }
}

// ---------------- aggregation (128-dim, bf16 payload) + bias + relu ----------
// TWO nodes per warp: lanes 0-15 -> node 2w, lanes 16-31 -> node 2w+1.
// Each lane gathers one uint4 (8 bf16) per edge; 16 lanes cover the 256B row.
// Two independent edge streams per warp + 4-deep unroll -> 8 gathers in flight.
__device__ __forceinline__ void bf16x8_add(float4& a, float4& b, uint4 v) {
    __nv_bfloat162 p0 = *reinterpret_cast<__nv_bfloat162*>(&v.x);
    __nv_bfloat162 p1 = *reinterpret_cast<__nv_bfloat162*>(&v.y);
    __nv_bfloat162 p2 = *reinterpret_cast<__nv_bfloat162*>(&v.z);
    __nv_bfloat162 p3 = *reinterpret_cast<__nv_bfloat162*>(&v.w);
    float2 f0 = __bfloat1622float2(p0);
    float2 f1 = __bfloat1622float2(p1);
    float2 f2 = __bfloat1622float2(p2);
    float2 f3 = __bfloat1622float2(p3);
    a.x += f0.x; a.y += f0.y; a.z += f1.x; a.w += f1.y;
    b.x += f2.x; b.y += f2.y; b.z += f3.x; b.w += f3.y;
}

__global__ void k_agg_relu128(const float* __restrict__ bias) {
    int warp = (blockIdx.x * blockDim.x + threadIdx.x) >> 5;
    int half = (threadIdx.x >> 4) & 1;
    int node = warp * 2 + half;
    if (node >= NN) return;
    int hl = threadIdx.x & 15;          // lane within half-warp
    const uint4* __restrict__ x = g_Zh; // row = 16 uint4
    int beg = g_rowbeg[node];
    int end = beg + g_counts[node];

    float4 aA0 = make_float4(0.f, 0.f, 0.f, 0.f);
    float4 aB0 = aA0, aA1 = aA0, aB1 = aA0;

    int e = beg;
    for (; e + 4 <= end; e += 4) {
        int s0 = __ldg(&g_esrc[e + 0]);
        int s1 = __ldg(&g_esrc[e + 1]);
        int s2 = __ldg(&g_esrc[e + 2]);
        int s3 = __ldg(&g_esrc[e + 3]);
        uint4 v0 = __ldg(&x[(size_t)s0 * 16 + hl]);
        uint4 v1 = __ldg(&x[(size_t)s1 * 16 + hl]);
        uint4 v2 = __ldg(&x[(size_t)s2 * 16 + hl]);
        uint4 v3 = __ldg(&x[(size_t)s3 * 16 + hl]);
        bf16x8_add(aA0, aB0, v0);
        bf16x8_add(aA1, aB1, v1);
        bf16x8_add(aA0, aB0, v2);
        bf16x8_add(aA1, aB1, v3);
    }
    for (; e < end; e++) {
        int s = __ldg(&g_esrc[e]);
        uint4 v = __ldg(&x[(size_t)s * 16 + hl]);
        bf16x8_add(aA0, aB0, v);
    }
    const float4* b4 = (const float4*)bias;
    float4 bA = __ldg(&b4[hl * 2]);
    float4 bB = __ldg(&b4[hl * 2 + 1]);
    float4 rA, rB;
    rA.x = fmaxf((aA0.x + aA1.x) + bA.x, 0.f);
    rA.y = fmaxf((aA0.y + aA1.y) + bA.y, 0.f);
    rA.z = fmaxf((aA0.z + aA1.z) + bA.z, 0.f);
    rA.w = fmaxf((aA0.w + aA1.w) + bA.w, 0.f);
    rB.x = fmaxf((aB0.x + aB1.x) + bB.x, 0.f);
    rB.y = fmaxf((aB0.y + aB1.y) + bB.y, 0.f);
    rB.z = fmaxf((aB0.z + aB1.z) + bB.z, 0.f);
    rB.w = fmaxf((aB0.w + aB1.w) + bB.w, 0.f);
    float4* outp = (float4*)g_A;
    outp[(size_t)node * 32 + hl * 2]     = rA;
    outp[(size_t)node * 32 + hl * 2 + 1] = rB;
}

// ---------------- aggregation (40-dim, fp32) + bias + relu: g_Z -> d_out -----
__global__ void k_agg_relu40(const float* __restrict__ bias,
                             float* __restrict__ outp) {
    int gw = (blockIdx.x * blockDim.x + threadIdx.x) >> 5;
    if (gw >= NN) return;
    const float* __restrict__ z = g_Z;
    int lane = threadIdx.x & 31;
    int f2 = lane + 32;
    bool has2 = f2 < NCLS;
    int beg = g_rowbeg[gw];
    int end = beg + g_counts[gw];

    float acc0a = 0.f, acc0b = 0.f, acc1a = 0.f, acc1b = 0.f;
    int e = beg;
    for (; e + 2 <= end; e += 2) {
        int s0 = __ldg(&g_esrc[e + 0]);
        int s1 = __ldg(&g_esrc[e + 1]);
        const float* r0 = z + (size_t)s0 * NCLS;
        const float* r1 = z + (size_t)s1 * NCLS;
        acc0a += __ldg(r0 + lane);
        acc0b += __ldg(r1 + lane);
        if (has2) {
            acc1a += __ldg(r0 + f2);
            acc1b += __ldg(r1 + f2);
        }
    }
    if (e < end) {
        int s = __ldg(&g_esrc[e]);
        const float* r0 = z + (size_t)s * NCLS;
        acc0a += __ldg(r0 + lane);
        if (has2) acc1a += __ldg(r0 + f2);
    }
    float* orow = outp + (size_t)gw * NCLS;
    orow[lane] = fmaxf((acc0a + acc0b) + __ldg(bias + lane), 0.f);
    if (has2) orow[f2] = fmaxf((acc1a + acc1b) + __ldg(bias + f2), 0.f);
}

// ---------------- GEMM 128-col -> bf16 Z: Zh[M,128] = A[M,128] @ W[128,128] --
// BM=128, BN=128, BK=16, 256 threads, 8x8 per thread. Epilogue packs bf16.
__global__ void __launch_bounds__(256) k_gemm128(const float* __restrict__ Aext,
                                                 const float* __restrict__ W) {
    __shared__ float As[16][132];
    __shared__ float Bs[16][132];
    const float* __restrict__ A = Aext ? Aext : g_A;

    int t = threadIdx.x;
    int tx = t & 15, ty = t >> 4;
    int m0 = blockIdx.x * 128;

    float acc[8][8];
#pragma unroll
    for (int i = 0; i < 8; i++)
#pragma unroll
        for (int j = 0; j < 8; j++) acc[i][j] = 0.f;

    for (int kc = 0; kc < 8; kc++) {
#pragma unroll
        for (int i = 0; i < 2; i++) {
            int f = t + i * 256;
            int row = f >> 2, kq = f & 3;
            float4 v = make_float4(0.f, 0.f, 0.f, 0.f);
            if (m0 + row < NN)
                v = *(const float4*)(A + (size_t)(m0 + row) * KDIM + kc * 16 + kq * 4);
            As[kq * 4 + 0][row] = v.x;
            As[kq * 4 + 1][row] = v.y;
            As[kq * 4 + 2][row] = v.z;
            As[kq * 4 + 3][row] = v.w;
        }
#pragma unroll
        for (int i = 0; i < 2; i++) {
            int r = (t >> 5) + i * 8;
            int c = (t & 31) * 4;
            *(float4*)&Bs[r][c] = *(const float4*)(W + (size_t)(kc * 16 + r) * KDIM + c);
        }
        __syncthreads();
#pragma unroll
        for (int kk = 0; kk < 16; kk++) {
            float4 aA = *(const float4*)&As[kk][ty * 8];
            float4 aB = *(const float4*)&As[kk][ty * 8 + 4];
            float4 bA = *(const float4*)&Bs[kk][tx * 8];
            float4 bB = *(const float4*)&Bs[kk][tx * 8 + 4];
            float a[8] = {aA.x, aA.y, aA.z, aA.w, aB.x, aB.y, aB.z, aB.w};
            float b[8] = {bA.x, bA.y, bA.z, bA.w, bB.x, bB.y, bB.z, bB.w};
#pragma unroll
            for (int i = 0; i < 8; i++)
#pragma unroll
                for (int j = 0; j < 8; j++) acc[i][j] = fmaf(a[i], b[j], acc[i][j]);
        }
        __syncthreads();
    }
    // epilogue: pack 8 fp32 -> 8 bf16 (16 B = one uint4) per row
#pragma unroll
    for (int i = 0; i < 8; i++) {
        int row = m0 + ty * 8 + i;
        if (row < NN) {
            __nv_bfloat162 p0 = __floats2bfloat162_rn(acc[i][0], acc[i][1]);
            __nv_bfloat162 p1 = __floats2bfloat162_rn(acc[i][2], acc[i][3]);
            __nv_bfloat162 p2 = __floats2bfloat162_rn(acc[i][4], acc[i][5]);
            __nv_bfloat162 p3 = __floats2bfloat162_rn(acc[i][6], acc[i][7]);
            uint4 w;
            w.x = *reinterpret_cast<unsigned*>(&p0);
            w.y = *reinterpret_cast<unsigned*>(&p1);
            w.z = *reinterpret_cast<unsigned*>(&p2);
            w.w = *reinterpret_cast<unsigned*>(&p3);
            g_Zh[(size_t)row * 16 + tx] = w;
        }
    }
}

// ---------------- GEMM 40-col (fp32): g_A @ W3 -> g_Z ------------------------
__global__ void __launch_bounds__(256) k_gemm40(const float* __restrict__ W) {
    __shared__ float As[16][132];
    __shared__ float Bs[16][68];
    const float* __restrict__ A = g_A;
    float* __restrict__ C = g_Z;
    const int N = NCLS;

    int t = threadIdx.x;
    int tx = t & 15, ty = t >> 4;
    int m0 = blockIdx.x * 128;

    float acc[8][4];
#pragma unroll
    for (int i = 0; i < 8; i++)
#pragma unroll
        for (int j = 0; j < 4; j++) acc[i][j] = 0.f;

    for (int kc = 0; kc < 8; kc++) {
#pragma unroll
        for (int i = 0; i < 2; i++) {
            int f = t + i * 256;
            int row = f >> 2, kq = f & 3;
            float4 v = make_float4(0.f, 0.f, 0.f, 0.f);
            if (m0 + row < NN)
                v = *(const float4*)(A + (size_t)(m0 + row) * KDIM + kc * 16 + kq * 4);
            As[kq * 4 + 0][row] = v.x;
            As[kq * 4 + 1][row] = v.y;
            As[kq * 4 + 2][row] = v.z;
            As[kq * 4 + 3][row] = v.w;
        }
        {
            int r = t >> 4, cq = t & 15;
#pragma unroll
            for (int j = 0; j < 4; j++) {
                int col = cq * 4 + j;
                Bs[r][cq * 4 + j] = (col < N) ? W[(size_t)(kc * 16 + r) * N + col] : 0.f;
            }
        }
        __syncthreads();
#pragma unroll
        for (int kk = 0; kk < 16; kk++) {
            float4 aA = *(const float4*)&As[kk][ty * 8];
            float4 aB = *(const float4*)&As[kk][ty * 8 + 4];
            float4 bv = *(const float4*)&Bs[kk][tx * 4];
            float a[8] = {aA.x, aA.y, aA.z, aA.w, aB.x, aB.y, aB.z, aB.w};
            float b[4] = {bv.x, bv.y, bv.z, bv.w};
#pragma unroll
            for (int i = 0; i < 8; i++)
#pragma unroll
                for (int j = 0; j < 4; j++) acc[i][j] = fmaf(a[i], b[j], acc[i][j]);
        }
        __syncthreads();
    }
#pragma unroll
    for (int i = 0; i < 8; i++) {
        int row = m0 + ty * 8 + i;
        if (row < NN) {
#pragma unroll
            for (int j = 0; j < 4; j++) {
                int col = tx * 4 + j;
                if (col < N)
                    C[(size_t)row * N + col] = acc[i][j];
            }
        }
    }
}

// ---------------- launch ----------------
extern "C" void kernel_launch(void* const* d_in, const int* in_sizes, int n_in,
                              void* d_out, int out_size) {
    const float* feats = (const float*)d_in[0];
    const int*   src   = (const int*)d_in[1];
    const int*   dst   = (const int*)d_in[2];
    const float* W1 = (const float*)d_in[3];
    const float* b1 = (const float*)d_in[4];
    const float* W2 = (const float*)d_in[5];
    const float* b2 = (const float*)d_in[6];
    const float* W3 = (const float*)d_in[7];
    const float* b3 = (const float*)d_in[8];
    float* out = (float*)d_out;

    // One-time resource init (first call is the non-captured correctness run).
    static cudaStream_t s1 = nullptr;
    static cudaEvent_t  eFork = nullptr, eJoin = nullptr;
    if (!s1) {
        cudaStreamCreateWithFlags(&s1, cudaStreamNonBlocking);
        cudaEventCreateWithFlags(&eFork, cudaEventDisableTiming);
        cudaEventCreateWithFlags(&eJoin, cudaEventDisableTiming);
    }

    const int AGG128_BLOCKS = ((NN + 1) / 2 * 32 + 255) / 256;  // 2 nodes/warp
    const int AGG40_BLOCKS  = (NN * 32 + 255) / 256;            // 1 node/warp
    const int GB = (NN + 127) / 128;                            // 782

    // Fork: CSR build on s1, concurrent with GEMM1 on the main stream.
    cudaEventRecord(eFork, 0);
    cudaStreamWaitEvent(s1, eFork, 0);
    k_zero<<<(NN + 255) / 256, 256, 0, s1>>>();
    k_hist<<<(NE + 255) / 256, 256, 0, s1>>>(dst);
    k_base<<<(NN + 255) / 256, 256, 0, s1>>>();
    k_scatter<<<(NE + 255) / 256, 256, 0, s1>>>(src, dst);
    cudaEventRecord(eJoin, s1);

    // Main stream: Layer-1 GEMM needs only feats/W1 (independent of CSR).
    k_gemm128<<<GB, 256>>>(feats, W1);               // feats -> g_Zh (bf16)

    // Join: aggregation needs the CSR.
    cudaStreamWaitEvent(0, eJoin, 0);
    k_agg_relu128<<<AGG128_BLOCKS, 256>>>(b1);       // g_Zh -> g_A (fp32)
    // Layer 2
    k_gemm128<<<GB, 256>>>(nullptr, W2);             // g_A -> g_Zh (bf16)
    k_agg_relu128<<<AGG128_BLOCKS, 256>>>(b2);       // g_Zh -> g_A (fp32)
    // Layer 3: full fp32 (cheap; avoids compounding quantization)
    k_gemm40<<<GB, 256>>>(W3);                       // g_A -> g_Z (40-dim fp32)
    k_agg_relu40<<<AGG40_BLOCKS, 256>>>(b3, out);    // g_Z -> d_out
}